// round 6
// baseline (speedup 1.0000x reference)
#include <cuda_runtime.h>
#include <cstdint>

#define K  11
#define TT 512
#define BB 4096
#define NCHUNK (TT / 4)          // 128 chunks of 4 steps
#define IMPOSSIBLE_F (-10000.0f)

// Precomputed tables (written by setup kernel each launch; deterministic).
__device__ float g_transM[K * K];  // masked transitions (log domain, for score)
__device__ float g_A[K];           // exp(trans[i][0])        (-> O, all allowed)
__device__ float g_C[5];           // exp(trans[0][1+2j])     (O -> B_j)
__device__ float g_D[5];           // exp(trans[1+2j][2+2j])  (B_j -> I_j)
__device__ float g_F[5];           // exp(trans[2+2j][2+2j])  (I_j -> I_j)
__device__ float g_startM[K];
__device__ float g_endM[K];
__device__ int   g_u8mode;

__global__ void setup_kernel(const float* __restrict__ trans,
                             const float* __restrict__ startv,
                             const float* __restrict__ endv,
                             const void*  __restrict__ maskp,
                             float* __restrict__ out) {
    int t = threadIdx.x;
    if (t < K * K) {
        int i = t / K, j = t % K;
        bool allowed = (j == 0) || (j & 1) || (i == j - 1) || (i == j);
        g_transM[t] = allowed ? trans[t] : IMPOSSIBLE_F;
    }
    if (t < K) {
        g_A[t] = expf(trans[t * K]);           // into O: always allowed
        bool sforb = (t >= 2) && !(t & 1);     // cannot start with I_i
        g_startM[t] = sforb ? IMPOSSIBLE_F : startv[t];
        g_endM[t]   = endv[t];
    }
    if (t < 5) {
        int bj = 1 + 2 * t, ij = 2 + 2 * t;
        g_C[t] = expf(trans[0 * K + bj]);
        g_D[t] = expf(trans[bj * K + ij]);
        g_F[t] = expf(trans[ij * K + ij]);
    }
    if (t == 0) {
        // lengths >= 256 so mask[0][1] true; byte[1]!=0 iff 1-byte bool buffer
        g_u8mode = (((const unsigned char*)maskp)[1] != 0) ? 1 : 0;
        out[0] = 0.0f;
    }
}

// Extract float #N (compile-time) from a float4[11] chunk window.
#define GETF(Q, N) (((N) & 3) == 0 ? Q[(N) >> 2].x : ((N) & 3) == 1 ? Q[(N) >> 2].y \
                  : ((N) & 3) == 2 ? Q[(N) >> 2].z : Q[(N) >> 2].w)
#define GETI(TQ, KK) ((KK) == 0 ? (TQ).x : (KK) == 1 ? (TQ).y : (KK) == 2 ? (TQ).z : (TQ).w)

// Select e[tg] from step registers via SEL tree (ALU pipe; avoids gather LDG).
#define PICK(TG) ((TG) < 4 ? ((TG) < 2 ? ((TG) == 0 ? e0_ : e1_)                    \
                                       : ((TG) == 2 ? e2_ : e3_))                   \
                 : ((TG) < 8 ? ((TG) < 6 ? ((TG) == 4 ? e4_ : e5_)                  \
                                         : ((TG) == 6 ? e6_ : e7_))                 \
                             : ((TG) < 10 ? ((TG) == 8 ? e8_ : e9_) : e10_)))

#define LOADC(Q, TQ, CI)                                                     \
    {                                                                        \
        int c_ = (CI); c_ = (c_ < NCHUNK) ? c_ : (NCHUNK - 1);               \
        const float4* p_ = e4 + c_ * 11;                                     \
        _Pragma("unroll") for (int q_ = 0; q_ < 11; q_++) Q[q_] = p_[q_];    \
        TQ = *(const int4*)(trow + c_ * 4);                                  \
    }

// One CRF step. Sparse BIO matvec in registers; SEL-freeze past len.
#define STEP(Q, TQ, T0, KK)                                                  \
    {                                                                        \
        const int t_ = (T0) + (KK);                                          \
        float e0_ = GETF(Q, (KK)*11 + 0),  e1_ = GETF(Q, (KK)*11 + 1);       \
        float e2_ = GETF(Q, (KK)*11 + 2),  e3_ = GETF(Q, (KK)*11 + 3);       \
        float e4_ = GETF(Q, (KK)*11 + 4),  e5_ = GETF(Q, (KK)*11 + 5);       \
        float e6_ = GETF(Q, (KK)*11 + 6),  e7_ = GETF(Q, (KK)*11 + 7);       \
        float e8_ = GETF(Q, (KK)*11 + 8),  e9_ = GETF(Q, (KK)*11 + 9);       \
        float e10_ = GETF(Q, (KK)*11 + 10);                                  \
        float p0_ = __expf(e0_), p1_ = __expf(e1_), p2_ = __expf(e2_);       \
        float p3_ = __expf(e3_), p4_ = __expf(e4_), p5_ = __expf(e5_);       \
        float p6_ = __expf(e6_), p7_ = __expf(e7_), p8_ = __expf(e8_);       \
        float p9_ = __expf(e9_), p10_ = __expf(e10_);                        \
        float ch0_ = r0 * cA0;                                               \
        float ch1_ = r1 * cA1;                                               \
        ch0_ = fmaf(r2, cA2, ch0_);   ch1_ = fmaf(r3, cA3, ch1_);            \
        ch0_ = fmaf(r4, cA4, ch0_);   ch1_ = fmaf(r5, cA5, ch1_);            \
        ch0_ = fmaf(r6, cA6, ch0_);   ch1_ = fmaf(r7, cA7, ch1_);            \
        ch0_ = fmaf(r8, cA8, ch0_);   ch1_ = fmaf(r9, cA9, ch1_);            \
        ch0_ = fmaf(r10, cA10, ch0_);                                        \
        float n0_  = (ch0_ + ch1_) * p0_;                                    \
        float n1_  = (r0 * cC0) * p1_;                                       \
        float n3_  = (r0 * cC1) * p3_;                                       \
        float n5_  = (r0 * cC2) * p5_;                                       \
        float n7_  = (r0 * cC3) * p7_;                                       \
        float n9_  = (r0 * cC4) * p9_;                                       \
        float n2_  = fmaf(r1, cD0, r2  * cF0) * p2_;                         \
        float n4_  = fmaf(r3, cD1, r4  * cF1) * p4_;                         \
        float n6_  = fmaf(r5, cD2, r6  * cF2) * p6_;                         \
        float n8_  = fmaf(r7, cD3, r8  * cF3) * p8_;                         \
        float n10_ = fmaf(r9, cD4, r10 * cF4) * p10_;                        \
        const bool vl_ = (t_ < len);                                         \
        r0 = vl_ ? n0_ : r0;   r1 = vl_ ? n1_ : r1;   r2 = vl_ ? n2_ : r2;   \
        r3 = vl_ ? n3_ : r3;   r4 = vl_ ? n4_ : r4;   r5 = vl_ ? n5_ : r5;   \
        r6 = vl_ ? n6_ : r6;   r7 = vl_ ? n7_ : r7;   r8 = vl_ ? n8_ : r8;   \
        r9 = vl_ ? n9_ : r9;   r10 = vl_ ? n10_ : r10;                       \
        int tg_ = GETI(TQ, KK);                                              \
        if (vl_) {                                                           \
            score += sh_trans[ptag * K + tg_] + PICK(tg_);                   \
            ptag = tg_;                                                      \
        }                                                                    \
    }

// Chunk renorm by state O. Invariant A0 + log(rho * x) preserved, so it is
// harmless for frozen lanes too.
#define RENORM                                                               \
    {                                                                        \
        float m_ = r0; float i_ = __frcp_rn(m_);                             \
        r0 = 1.0f;                                                           \
        r1 *= i_; r2 *= i_; r3 *= i_; r4 *= i_; r5 *= i_;                    \
        r6 *= i_; r7 *= i_; r8 *= i_; r9 *= i_; r10 *= i_;                   \
        A0 += __logf(m_);                                                    \
    }

#define PROC(Q, TQ, CI)                                                      \
    {                                                                        \
        const int tb_ = (CI) * 4;                                            \
        STEP(Q, TQ, tb_, 0) STEP(Q, TQ, tb_, 1)                              \
        STEP(Q, TQ, tb_, 2) STEP(Q, TQ, tb_, 3)                              \
        RENORM                                                               \
    }

// One batch row per thread: no shuffles, no smem on the recurrence.
__global__ void __launch_bounds__(32, 1)
crf_kernel(const float* __restrict__ em,
           const void*  __restrict__ maskp,
           const int*   __restrict__ tags,
           float* __restrict__ out) {
    __shared__ float sh_trans[K * K];
    __shared__ float sh_start[K];
    __shared__ float sh_end[K];
    {
        int tix = threadIdx.x;
        for (int i = tix; i < K * K; i += 32) sh_trans[i] = g_transM[i];
        if (tix < K) { sh_start[tix] = g_startM[tix]; sh_end[tix] = g_endM[tix]; }
    }
    __syncwarp();

    const int b = blockIdx.x * 32 + threadIdx.x;
    const float4* e4  = (const float4*)(em + (size_t)b * TT * K);
    const int*   trow = tags + (size_t)b * TT;

    // Sequence length = popcount of this row's prefix mask.
    int len = 0;
    if (g_u8mode) {
        const uint4* m4 = (const uint4*)((const unsigned char*)maskp + (size_t)b * TT);
        unsigned acc = 0u;
#pragma unroll
        for (int i = 0; i < TT / 16; i++) {
            uint4 x = m4[i];
            acc = __dp4a(x.x, 0x01010101u, acc);
            acc = __dp4a(x.y, 0x01010101u, acc);
            acc = __dp4a(x.z, 0x01010101u, acc);
            acc = __dp4a(x.w, 0x01010101u, acc);
        }
        len = (int)acc;
    } else {
        const uint4* m4 = (const uint4*)((const unsigned*)maskp + (size_t)b * TT);
        for (int i = 0; i < TT / 4; i++) {
            uint4 x = m4[i];
            len += (x.x != 0u) + (x.y != 0u) + (x.z != 0u) + (x.w != 0u);
        }
    }

    // Sparse transition coefficients (26 registers).
    const float cA0 = g_A[0], cA1 = g_A[1], cA2 = g_A[2], cA3 = g_A[3];
    const float cA4 = g_A[4], cA5 = g_A[5], cA6 = g_A[6], cA7 = g_A[7];
    const float cA8 = g_A[8], cA9 = g_A[9], cA10 = g_A[10];
    const float cC0 = g_C[0], cC1 = g_C[1], cC2 = g_C[2], cC3 = g_C[3], cC4 = g_C[4];
    const float cD0 = g_D[0], cD1 = g_D[1], cD2 = g_D[2], cD3 = g_D[3], cD4 = g_D[4];
    const float cF0 = g_F[0], cF1 = g_F[1], cF2 = g_F[2], cF3 = g_F[3], cF4 = g_F[4];

    // Triple-buffered chunk windows (prefetch distance ~8 steps).
    float4 QA[11], QB[11], QC[11];
    int4 TA, TBv, TCv;
    LOADC(QA, TA, 0)
    LOADC(QB, TBv, 1)
    LOADC(QC, TCv, 2)

    float r0, r1, r2, r3, r4, r5, r6, r7, r8, r9, r10, A0, score;
    int ptag;
    {
        // t = 0 (start), then steps 1..3 of chunk 0.
        float e0_ = GETF(QA, 0), e1_ = GETF(QA, 1), e2_ = GETF(QA, 2);
        float e3_ = GETF(QA, 3), e4_ = GETF(QA, 4), e5_ = GETF(QA, 5);
        float e6_ = GETF(QA, 6), e7_ = GETF(QA, 7), e8_ = GETF(QA, 8);
        float e9_ = GETF(QA, 9), e10_ = GETF(QA, 10);
        float aO_ = sh_start[0] + e0_;
        A0 = aO_;
        r0 = 1.0f;
        r1  = __expf(sh_start[1]  + e1_  - aO_);
        r2  = __expf(sh_start[2]  + e2_  - aO_);   // start -10000 -> exactly 0
        r3  = __expf(sh_start[3]  + e3_  - aO_);
        r4  = __expf(sh_start[4]  + e4_  - aO_);
        r5  = __expf(sh_start[5]  + e5_  - aO_);
        r6  = __expf(sh_start[6]  + e6_  - aO_);
        r7  = __expf(sh_start[7]  + e7_  - aO_);
        r8  = __expf(sh_start[8]  + e8_  - aO_);
        r9  = __expf(sh_start[9]  + e9_  - aO_);
        r10 = __expf(sh_start[10] + e10_ - aO_);
        ptag  = TA.x;
        score = sh_start[ptag] + PICK(ptag);
        STEP(QA, TA, 0, 1)
        STEP(QA, TA, 0, 2)
        STEP(QA, TA, 0, 3)
        RENORM
    }

    // Chunks 1..127: 42 rotations of 3 + final chunk.
    int c = 1;
#pragma unroll 1
    for (int it = 0; it < 42; it++) {
        LOADC(QA, TA, c + 2)  PROC(QB, TBv, c)
        LOADC(QB, TBv, c + 3) PROC(QC, TCv, c + 1)
        LOADC(QC, TCv, c + 4) PROC(QA, TA, c + 2)
        c += 3;
    }
    PROC(QB, TBv, 127)   // c == 127; QB holds chunk 127

    // z = A0 + log( sum_j rho_j * exp(end_j) )
    float v0 = fmaf(r1, __expf(sh_end[1]), r0 * __expf(sh_end[0]));
    float v1 = fmaf(r3, __expf(sh_end[3]), r2 * __expf(sh_end[2]));
    float v2 = fmaf(r5, __expf(sh_end[5]), r4 * __expf(sh_end[4]));
    float v3 = fmaf(r7, __expf(sh_end[7]), r6 * __expf(sh_end[6]));
    float v4 = fmaf(r9, __expf(sh_end[9]), r8 * __expf(sh_end[8]));
    float v5 = r10 * __expf(sh_end[10]);
    float z = A0 + __logf(((v0 + v1) + (v2 + v3)) + (v4 + v5));

    score += sh_end[ptag];
    float nll = (score - z) * (1.0f / (float)BB);

#pragma unroll
    for (int k = 16; k; k >>= 1) nll += __shfl_xor_sync(0xFFFFFFFFu, nll, k);
    if (threadIdx.x == 0) atomicAdd(out, nll);
}

extern "C" void kernel_launch(void* const* d_in, const int* in_sizes, int n_in,
                              void* d_out, int out_size) {
    const float* em     = (const float*)d_in[0];
    const void*  maskp  = d_in[1];
    const int*   tags   = (const int*)d_in[2];
    const float* trans  = (const float*)d_in[3];
    const float* startv = (const float*)d_in[4];
    const float* endv   = (const float*)d_in[5];
    float* out = (float*)d_out;

    setup_kernel<<<1, 128>>>(trans, startv, endv, maskp, out);
    crf_kernel<<<BB / 32, 32>>>(em, maskp, tags, out);
}

// round 8
// speedup vs baseline: 1.5198x; 1.5198x over previous
#include <cuda_runtime.h>
#include <cstdint>

#define K  11
#define TT 512
#define BB 4096
#define IMPOSSIBLE_F (-10000.0f)

// Precomputed tables (written by setup kernel each launch; deterministic).
__device__ float g_transM[K * K];   // masked transitions (log, for score)
__device__ float g_expT[K * K];     // exp(masked transitions)
__device__ float g_startM[K];
__device__ float g_endM[K];
__device__ int   g_u8mode;

// Per-row scratch: alpha/beta states at the t=255 boundary + partial scores.
__device__ float g_ra[K][BB];
__device__ float g_rb[K][BB];
__device__ float g_A0a[BB];
__device__ float g_A0b[BB];
__device__ float g_sca[BB];
__device__ float g_scb[BB];

__global__ void setup_kernel(const float* __restrict__ trans,
                             const float* __restrict__ startv,
                             const float* __restrict__ endv,
                             const void*  __restrict__ maskp,
                             float* __restrict__ out) {
    int t = threadIdx.x;
    if (t < K * K) {
        int i = t / K, j = t % K;
        bool allowed = (j == 0) || (j & 1) || (i == j - 1) || (i == j);
        float v = allowed ? trans[t] : IMPOSSIBLE_F;
        g_transM[t] = v;
        g_expT[t]   = expf(v);   // exp(-10000) underflows to exactly 0
    }
    if (t < K) {
        bool sforb = (t >= 2) && !(t & 1);   // cannot start with I_i
        g_startM[t] = sforb ? IMPOSSIBLE_F : startv[t];
        g_endM[t]   = endv[t];
    }
    if (t == 0) {
        // lengths >= 256 so mask[0][1] true; byte[1]!=0 iff 1-byte bool buffer
        g_u8mode = (((const unsigned char*)maskp)[1] != 0) ? 1 : 0;
        out[0] = 0.0f;
    }
}

#define FULLM 0xFFFFFFFFu

// ---- shared step machinery (8-lane groups, lane owns states lane and lane+8) ----

#define BCAST11(DST, XA, XB)                                             \
    float DST##0  = __shfl_sync(FULLM, XA, 0, 8);                        \
    float DST##1  = __shfl_sync(FULLM, XA, 1, 8);                        \
    float DST##2  = __shfl_sync(FULLM, XA, 2, 8);                        \
    float DST##3  = __shfl_sync(FULLM, XA, 3, 8);                        \
    float DST##4  = __shfl_sync(FULLM, XA, 4, 8);                        \
    float DST##5  = __shfl_sync(FULLM, XA, 5, 8);                        \
    float DST##6  = __shfl_sync(FULLM, XA, 6, 8);                        \
    float DST##7  = __shfl_sync(FULLM, XA, 7, 8);                        \
    float DST##8  = __shfl_sync(FULLM, XB, 0, 8);                        \
    float DST##9  = __shfl_sync(FULLM, XB, 1, 8);                        \
    float DST##10 = __shfl_sync(FULLM, XB, 2, 8);

#define DOT11(RES, V, C)                                                 \
    float RES;                                                           \
    {                                                                    \
        float d0_ = V##0 * C[0];                                         \
        float d1_ = V##1 * C[1];                                         \
        d0_ = fmaf(V##2,  C[2],  d0_);  d1_ = fmaf(V##3,  C[3],  d1_);   \
        d0_ = fmaf(V##4,  C[4],  d0_);  d1_ = fmaf(V##5,  C[5],  d1_);   \
        d0_ = fmaf(V##6,  C[6],  d0_);  d1_ = fmaf(V##7,  C[7],  d1_);   \
        d0_ = fmaf(V##8,  C[8],  d0_);  d1_ = fmaf(V##9,  C[9],  d1_);   \
        d0_ = fmaf(V##10, C[10], d0_);                                   \
        RES = d0_ + d1_;                                                 \
    }

#define RENORM                                                           \
    {                                                                    \
        float m_ = __shfl_sync(FULLM, rhoA, 0, 8);                       \
        float i_ = __frcp_rn(m_);                                        \
        rhoA *= i_; rhoB *= i_;                                          \
        A0 += __logf(m_);                                                \
    }

// ---- alpha (forward) ----

#define ALOADC(QA_, QB_, QT_, TB)                                        \
    {                                                                    \
        _Pragma("unroll")                                                \
        for (int k_ = 0; k_ < 8; k_++) {                                 \
            int t_ = (TB) + k_;                                          \
            QA_[k_] = erow[t_ * K + sA];                                 \
            QB_[k_] = erow[t_ * K + sB];                                 \
            QT_[k_] = trow[t_];                                          \
        }                                                                \
    }

#define ASTEP(QA_, QB_, QT_, KK)                                         \
    {                                                                    \
        float emA_ = QA_[KK], emB_ = QB_[KK];                            \
        BCAST11(r_, rhoA, rhoB)                                          \
        DOT11(sa_, r_, cA)                                               \
        DOT11(sb_, r_, cB)                                               \
        float peA_ = __expf(emA_), peB_ = __expf(emB_);                  \
        rhoA = sa_ * peA_;                                               \
        rhoB = sb_ * peB_;                                               \
        int tg_ = QT_[KK];                                               \
        transacc += sh_trans[ptag * K + tg_];                            \
        emacc += (tg_ == sA)  ? emA_ : 0.0f;                             \
        emacc += (tg_ == sBc) ? emB_ : 0.0f;                             \
        ptag = tg_;                                                      \
    }

#define APROC(QA_, QB_, QT_)                                             \
    {                                                                    \
        ASTEP(QA_, QB_, QT_, 0) ASTEP(QA_, QB_, QT_, 1)                  \
        ASTEP(QA_, QB_, QT_, 2) ASTEP(QA_, QB_, QT_, 3)                  \
        ASTEP(QA_, QB_, QT_, 4) ASTEP(QA_, QB_, QT_, 5)                  \
        ASTEP(QA_, QB_, QT_, 6) ASTEP(QA_, QB_, QT_, 7)                  \
        RENORM                                                           \
    }

// ---- beta (backward); chunk base EB covers em indices [EB, EB+7], consumed
// descending. Step kk uses em_{t+1} at index EB+7-kk, tag pair (t, t+1). ----

#define BLOADC(QA_, QB_, QT_, EB)                                        \
    {                                                                    \
        _Pragma("unroll")                                                \
        for (int k_ = 0; k_ < 8; k_++) {                                 \
            int t_ = (EB) + k_;                                          \
            QA_[k_] = erow[t_ * K + sA];                                 \
            QB_[k_] = erow[t_ * K + sB];                                 \
            QT_[k_] = trow[t_ - 1];                                      \
        }                                                                \
    }

#define BSTEP(QA_, QB_, QT_, EB, KK)                                     \
    {                                                                    \
        float emA_ = QA_[7 - (KK)], emB_ = QB_[7 - (KK)];                \
        float btA_ = __expf(emA_) * rhoA;                                \
        float btB_ = __expf(emB_) * rhoB;                                \
        BCAST11(bt_, btA_, btB_)                                         \
        DOT11(na_, bt_, rA)                                              \
        DOT11(nb_, bt_, rB)                                              \
        const bool vl_ = ((EB) + 7 - (KK)) < len;    /* t+1 < len */     \
        int tg_ = QT_[7 - (KK)];                     /* tag at t  */     \
        transacc += vl_ ? sh_trans[tg_ * K + ntag] : 0.0f;               \
        emacc += (vl_ && ntag == sA)  ? emA_ : 0.0f;                     \
        emacc += (vl_ && ntag == sBc) ? emB_ : 0.0f;                     \
        ntag = vl_ ? tg_ : ntag;                                         \
        rhoA = vl_ ? na_ : rhoA;                                         \
        rhoB = vl_ ? nb_ : rhoB;                                         \
    }

#define BPROC(QA_, QB_, QT_, EB)                                         \
    {                                                                    \
        BSTEP(QA_, QB_, QT_, EB, 0) BSTEP(QA_, QB_, QT_, EB, 1)          \
        BSTEP(QA_, QB_, QT_, EB, 2) BSTEP(QA_, QB_, QT_, EB, 3)          \
        BSTEP(QA_, QB_, QT_, EB, 4) BSTEP(QA_, QB_, QT_, EB, 5)          \
        BSTEP(QA_, QB_, QT_, EB, 6) BSTEP(QA_, QB_, QT_, EB, 7)          \
        RENORM                                                           \
    }

// Blocks [0,128): alpha halves.  Blocks [128,256): beta halves.
// 8 warps/block, 4 groups of 8 lanes per warp -> 32 rows per block.
__global__ void __launch_bounds__(256)
crf_kernel(const float* __restrict__ em,
           const void*  __restrict__ maskp,
           const int*   __restrict__ tags) {
    __shared__ float sh_trans[K * K];
    __shared__ float sh_start[K];
    __shared__ float sh_end[K];
    {
        int i = threadIdx.x;
        if (i < K * K) sh_trans[i] = g_transM[i];
        if (i >= 128 && i < 128 + K) {
            sh_start[i - 128] = g_startM[i - 128];
            sh_end[i - 128]   = g_endM[i - 128];
        }
    }
    __syncthreads();

    const int tid  = threadIdx.x;
    const int lane = tid & 7;
    const int b    = (blockIdx.x & 127) * 32 + (tid >> 3);
    const bool isBeta = blockIdx.x >= 128;

    const int  sA   = lane;
    const bool hasB = lane < 3;
    const int  sB   = hasB ? lane + 8 : lane;   // clamped for safe loads
    const int  sBc  = hasB ? lane + 8 : -1;     // for comparisons

    const float* erow = em   + (size_t)b * TT * K;
    const int*   trow = tags + (size_t)b * TT;

    float rhoA, rhoB, A0, transacc, emacc;
    int ptag;
    float QXa[8], QXb[8], QYa[8], QYb[8];
    int   QXt[8], QYt[8];

    if (!isBeta) {
        // ---------- forward over t in [0, 255] ----------
        float cA[K], cB[K];
#pragma unroll
        for (int i = 0; i < K; i++) {
            cA[i] = g_expT[i * K + sA];
            cB[i] = hasB ? g_expT[i * K + sB] : 0.0f;
        }

        ALOADC(QXa, QXb, QXt, 0)
        {
            float aA = sh_start[sA] + QXa[0];
            float aB = sh_start[sB] + QXb[0];
            float a0 = __shfl_sync(FULLM, aA, 0, 8);
            rhoA = __expf(aA - a0);
            rhoB = hasB ? __expf(aB - a0) : 0.0f;
            A0 = a0;
            int tg = QXt[0];
            transacc = sh_start[tg];
            emacc = 0.0f;
            emacc += (tg == sA)  ? QXa[0] : 0.0f;
            emacc += (tg == sBc) ? QXb[0] : 0.0f;
            ptag = tg;
        }
        ALOADC(QYa, QYb, QYt, 8)
        ASTEP(QXa, QXb, QXt, 1) ASTEP(QXa, QXb, QXt, 2)
        ASTEP(QXa, QXb, QXt, 3) ASTEP(QXa, QXb, QXt, 4)
        ASTEP(QXa, QXb, QXt, 5) ASTEP(QXa, QXb, QXt, 6)
        ASTEP(QXa, QXb, QXt, 7)
        RENORM
#pragma unroll 1
        for (int cc = 0; cc < 15; cc++) {
            ALOADC(QXa, QXb, QXt, 16 + 16 * cc)
            APROC(QYa, QYb, QYt)
            ALOADC(QYa, QYb, QYt, 24 + 16 * cc)
            APROC(QXa, QXb, QXt)
        }
        APROC(QYa, QYb, QYt)   // t = 248..255

        float ema = emacc;
        ema += __shfl_xor_sync(FULLM, ema, 1, 8);
        ema += __shfl_xor_sync(FULLM, ema, 2, 8);
        ema += __shfl_xor_sync(FULLM, ema, 4, 8);
        g_ra[sA][b] = rhoA;
        if (hasB) g_ra[sB][b] = rhoB;
        if (lane == 0) { g_A0a[b] = A0; g_sca[b] = transacc + ema; }
    } else {
        // ---------- backward from the end down to the t=255 boundary ----------
        float rA[K], rB[K];
#pragma unroll
        for (int i = 0; i < K; i++) {
            rA[i] = g_expT[sA * K + i];
            rB[i] = hasB ? g_expT[sB * K + i] : 0.0f;
        }

        // row length = popcount of prefix mask
        int len = 0;
        if (g_u8mode) {
            const uint4* m4 = (const uint4*)((const unsigned char*)maskp + (size_t)b * TT);
            unsigned acc = 0u;
#pragma unroll
            for (int i = lane; i < TT / 16; i += 8) {
                uint4 x = m4[i];
                acc = __dp4a(x.x, 0x01010101u, acc);
                acc = __dp4a(x.y, 0x01010101u, acc);
                acc = __dp4a(x.z, 0x01010101u, acc);
                acc = __dp4a(x.w, 0x01010101u, acc);
            }
            len = (int)acc;
        } else {
            const uint4* m4 = (const uint4*)((const unsigned*)maskp + (size_t)b * TT);
            for (int i = lane; i < TT / 4; i += 8) {
                uint4 x = m4[i];
                len += (x.x != 0u) + (x.y != 0u) + (x.z != 0u) + (x.w != 0u);
            }
        }
        len += __shfl_xor_sync(FULLM, len, 1, 8);
        len += __shfl_xor_sync(FULLM, len, 2, 8);
        len += __shfl_xor_sync(FULLM, len, 4, 8);

        const int lastTag = trow[len - 1];
        rhoA = __expf(sh_end[sA]);
        rhoB = hasB ? __expf(sh_end[sB]) : 0.0f;
        A0 = 0.0f;
        transacc = 0.0f;
        emacc = 0.0f;
        int ntag = lastTag;   // tag at position t+1 for the first valid step
        ptag = 0; (void)ptag;

        BLOADC(QXa, QXb, QXt, 504)
        BLOADC(QYa, QYb, QYt, 496)
#pragma unroll 1
        for (int cc = 0; cc < 15; cc++) {
            int ebx = 504 - 16 * cc;
            BPROC(QXa, QXb, QXt, ebx)
            BLOADC(QXa, QXb, QXt, ebx - 16)
            BPROC(QYa, QYb, QYt, ebx - 8)
            BLOADC(QYa, QYb, QYt, ebx - 24)
        }
        BPROC(QXa, QXb, QXt, 264)
        BPROC(QYa, QYb, QYt, 256)    // produces beta at t = 255

        float emb = emacc;
        emb += __shfl_xor_sync(FULLM, emb, 1, 8);
        emb += __shfl_xor_sync(FULLM, emb, 2, 8);
        emb += __shfl_xor_sync(FULLM, emb, 4, 8);
        g_rb[sA][b] = rhoA;
        if (hasB) g_rb[sB][b] = rhoB;
        if (lane == 0) {
            g_A0b[b] = A0;
            g_scb[b] = transacc + emb + sh_end[lastTag];
        }
    }
}

// Per-row combine: Z = A0a + A0b + log(sum_s ra[s]*rb[s]); reduce mean NLL.
__global__ void __launch_bounds__(256)
combine_kernel(float* __restrict__ out) {
    int r = blockIdx.x * 256 + threadIdx.x;
    float dot = 0.0f;
#pragma unroll
    for (int s = 0; s < K; s++) dot = fmaf(g_ra[s][r], g_rb[s][r], dot);
    float z = g_A0a[r] + g_A0b[r] + __logf(dot);
    float nll = (g_sca[r] + g_scb[r] - z) * (1.0f / (float)BB);
#pragma unroll
    for (int k = 16; k; k >>= 1) nll += __shfl_xor_sync(FULLM, nll, k);
    if ((threadIdx.x & 31) == 0) atomicAdd(out, nll);
}

extern "C" void kernel_launch(void* const* d_in, const int* in_sizes, int n_in,
                              void* d_out, int out_size) {
    const float* em     = (const float*)d_in[0];
    const void*  maskp  = d_in[1];
    const int*   tags   = (const int*)d_in[2];
    const float* trans  = (const float*)d_in[3];
    const float* startv = (const float*)d_in[4];
    const float* endv   = (const float*)d_in[5];
    float* out = (float*)d_out;

    setup_kernel<<<1, 128>>>(trans, startv, endv, maskp, out);
    crf_kernel<<<256, 256>>>(em, maskp, tags);
    combine_kernel<<<BB / 256, 256>>>(out);
}

// round 9
// speedup vs baseline: 1.5978x; 1.0513x over previous
#include <cuda_runtime.h>
#include <cstdint>

#define K  11
#define TT 512
#define BB 4096
#define IMPOSSIBLE_F (-10000.0f)
#define FULLM 0xFFFFFFFFu

// Precomputed tables (written by setup kernel each launch; deterministic).
__device__ float g_transM[K * K];   // masked transitions (log, for score)
__device__ float g_expT[K * K];     // exp(masked transitions)
__device__ float g_startM[K];
__device__ float g_endM[K];
__device__ int   g_u8mode;
__device__ int   g_done;            // block-completion ticket

// Per-row scratch: alpha/beta states at the t=255 boundary + partial scores.
__device__ float g_ra[K][BB];
__device__ float g_rb[K][BB];
__device__ float g_A0a[BB];
__device__ float g_A0b[BB];
__device__ float g_sca[BB];
__device__ float g_scb[BB];

__global__ void setup_kernel(const float* __restrict__ trans,
                             const float* __restrict__ startv,
                             const float* __restrict__ endv,
                             const void*  __restrict__ maskp,
                             float* __restrict__ out) {
    int t = threadIdx.x;
    if (t < K * K) {
        int i = t / K, j = t % K;
        bool allowed = (j == 0) || (j & 1) || (i == j - 1) || (i == j);
        float v = allowed ? trans[t] : IMPOSSIBLE_F;
        g_transM[t] = v;
        g_expT[t]   = expf(v);   // exp(-10000) underflows to exactly 0
    }
    if (t < K) {
        bool sforb = (t >= 2) && !(t & 1);   // cannot start with I_i
        g_startM[t] = sforb ? IMPOSSIBLE_F : startv[t];
        g_endM[t]   = endv[t];
    }
    if (t == 0) {
        // lengths >= 256 so mask[0][1] true; byte[1]!=0 iff 1-byte bool buffer
        g_u8mode = (((const unsigned char*)maskp)[1] != 0) ? 1 : 0;
        g_done = 0;
        out[0] = 0.0f;
    }
}

#define CMP(V, I) ((I) == 0 ? (V).x : (I) == 1 ? (V).y : (I) == 2 ? (V).z : (V).w)
#define TAG8(TL_, TH_, KK) ((KK) < 4 ? CMP(TL_, KK) : CMP(TH_, (KK) - 4))
// beta tag for step KK: logical index 6-KK relative to EB; -1 -> scalar TLw
#define BTAG(TLw_, TM_, TH_, KK) ((KK) == 7 ? (TLw_) : (6 - (KK)) < 4 ? CMP(TM_, 6 - (KK)) : CMP(TH_, 2 - (KK)))

#define RENORM                                                           \
    {                                                                    \
        float m_ = __shfl_sync(FULLM, rhoA, 0, 8);                       \
        float i_ = __frcp_rn(m_);                                        \
        rhoA *= i_; rhoB *= i_;                                          \
        A0 += __logf(m_);                                                \
    }

// ---- alpha (forward), sparse BIO matvec: 6 shuffles/step ----
#define ASTEP(EMA, EMB, TG)                                              \
    {                                                                    \
        float rr_  = __shfl_sync(FULLM, rhoA, rotA_, 8);  /* lane-1 */   \
        float r0_  = __shfl_sync(FULLM, rhoA, 0, 8);                     \
        float rb1_ = __shfl_sync(FULLM, rhoB, 1, 8);                     \
        float p_ = fmaf(rhoB, wOb, rhoA * wOa);                          \
        p_ += __shfl_xor_sync(FULLM, p_, 1, 8);                          \
        p_ += __shfl_xor_sync(FULLM, p_, 2, 8);                          \
        p_ += __shfl_xor_sync(FULLM, p_, 4, 8);                          \
        float nA_ = isO ? p_                                             \
                  : (isOddA ? r0_ * cCa : fmaf(rr_, cDa, rhoA * cFa));   \
        float xb_ = isO ? rr_ : rb1_;                                    \
        float nB_ = isB9 ? r0_ * cC9 : fmaf(xb_, cDb, rhoB * cFb);       \
        float peA_ = __expf(EMA), peB_ = __expf(EMB);                    \
        rhoA = nA_ * peA_;                                               \
        rhoB = nB_ * peB_;                                               \
        int tg_ = (TG);                                                  \
        transacc += sh_trans[ptag * K + tg_];                            \
        emacc += (tg_ == sA)  ? (EMA) : 0.0f;                            \
        emacc += (tg_ == sBc) ? (EMB) : 0.0f;                            \
        ptag = tg_;                                                      \
    }

#define ALOADC(QA_, QB_, TL_, TH_, TB)                                   \
    {                                                                    \
        _Pragma("unroll")                                                \
        for (int k_ = 0; k_ < 8; k_++) {                                 \
            int t_ = (TB) + k_;                                          \
            QA_[k_] = erow[t_ * K + sA];                                 \
            QB_[k_] = erow[t_ * K + sB];                                 \
        }                                                                \
        TL_ = trow4[(TB) >> 2];                                          \
        TH_ = trow4[((TB) >> 2) + 1];                                    \
    }

#define APROC(QA_, QB_, TL_, TH_)                                        \
    {                                                                    \
        ASTEP(QA_[0], QB_[0], TAG8(TL_, TH_, 0))                         \
        ASTEP(QA_[1], QB_[1], TAG8(TL_, TH_, 1))                         \
        ASTEP(QA_[2], QB_[2], TAG8(TL_, TH_, 2))                         \
        ASTEP(QA_[3], QB_[3], TAG8(TL_, TH_, 3))                         \
        ASTEP(QA_[4], QB_[4], TAG8(TL_, TH_, 4))                         \
        ASTEP(QA_[5], QB_[5], TAG8(TL_, TH_, 5))                         \
        ASTEP(QA_[6], QB_[6], TAG8(TL_, TH_, 6))                         \
        ASTEP(QA_[7], QB_[7], TAG8(TL_, TH_, 7))                         \
        RENORM                                                           \
    }

// ---- beta (backward), sparse rows: 6 shuffles/step ----
#define BSTEP(EMA, EMB, TG, VALID)                                       \
    {                                                                    \
        float btA_ = __expf(EMA) * rhoA;                                 \
        float btB_ = __expf(EMB) * rhoB;                                 \
        float rot_ = __shfl_sync(FULLM, btA_, rotB_, 8);  /* lane+1 */   \
        float bt0_ = __shfl_sync(FULLM, btA_, 0, 8);                     \
        float vsh_ = __shfl_sync(FULLM, btB_, vsrc_, 8);                 \
        float q_ = fmaf(btB_, uOb, btA_ * uOa);                          \
        q_ += __shfl_xor_sync(FULLM, q_, 1, 8);                          \
        q_ += __shfl_xor_sync(FULLM, q_, 2, 8);                          \
        q_ += __shfl_xor_sync(FULLM, q_, 4, 8);                          \
        float xa_ = isOddA ? (is7 ? vsh_ : rot_) : btA_;                 \
        float nA_ = isO ? q_ : fmaf(bt0_, e0a, xa_ * exa);               \
        float xb_ = isB9 ? vsh_ : btB_;                                  \
        float nB_ = fmaf(bt0_, e0b, xb_ * exb);                          \
        const bool vl_ = (VALID);                                        \
        int tg_ = (TG);                                                  \
        transacc += vl_ ? sh_trans[tg_ * K + ntag] : 0.0f;               \
        emacc += (vl_ && ntag == sA)  ? (EMA) : 0.0f;                    \
        emacc += (vl_ && ntag == sBc) ? (EMB) : 0.0f;                    \
        ntag = vl_ ? tg_ : ntag;                                         \
        rhoA = vl_ ? nA_ : rhoA;                                         \
        rhoB = vl_ ? nB_ : rhoB;                                         \
    }

#define BLOADC(QA_, QB_, TLw_, TM_, TH_, EB)                             \
    {                                                                    \
        _Pragma("unroll")                                                \
        for (int k_ = 0; k_ < 8; k_++) {                                 \
            int t_ = (EB) + k_;                                          \
            QA_[k_] = erow[t_ * K + sA];                                 \
            QB_[k_] = erow[t_ * K + sB];                                 \
        }                                                                \
        TLw_ = trow[(EB) - 1];                                           \
        TM_  = trow4[(EB) >> 2];                                         \
        TH_  = trow4[((EB) >> 2) + 1];                                   \
    }

#define BPROC(QA_, QB_, TLw_, TM_, TH_, EB)                              \
    {                                                                    \
        BSTEP(QA_[7], QB_[7], BTAG(TLw_, TM_, TH_, 0), ((EB) + 7) < len) \
        BSTEP(QA_[6], QB_[6], BTAG(TLw_, TM_, TH_, 1), ((EB) + 6) < len) \
        BSTEP(QA_[5], QB_[5], BTAG(TLw_, TM_, TH_, 2), ((EB) + 5) < len) \
        BSTEP(QA_[4], QB_[4], BTAG(TLw_, TM_, TH_, 3), ((EB) + 4) < len) \
        BSTEP(QA_[3], QB_[3], BTAG(TLw_, TM_, TH_, 4), ((EB) + 3) < len) \
        BSTEP(QA_[2], QB_[2], BTAG(TLw_, TM_, TH_, 5), ((EB) + 2) < len) \
        BSTEP(QA_[1], QB_[1], BTAG(TLw_, TM_, TH_, 6), ((EB) + 1) < len) \
        BSTEP(QA_[0], QB_[0], BTAG(TLw_, TM_, TH_, 7), ((EB) + 0) < len) \
        RENORM                                                           \
    }

// Blocks [0,128): alpha halves (t in [0,255]).  Blocks [128,256): beta halves.
// 8 warps/block, 4 groups of 8 lanes per warp -> 32 rows per block.
// The LAST block to finish (atomic ticket) performs the per-row combine.
__global__ void __launch_bounds__(256)
crf_kernel(const float* __restrict__ em,
           const void*  __restrict__ maskp,
           const int*   __restrict__ tags,
           float* __restrict__ out) {
    __shared__ float sh_trans[K * K];
    __shared__ float sh_start[K];
    __shared__ float sh_end[K];
    __shared__ float sh_red[8];
    __shared__ int   sh_islast;
    {
        int i = threadIdx.x;
        if (i < K * K) sh_trans[i] = g_transM[i];
        if (i >= 128 && i < 128 + K) {
            sh_start[i - 128] = g_startM[i - 128];
            sh_end[i - 128]   = g_endM[i - 128];
        }
    }
    __syncthreads();

    const int tid  = threadIdx.x;
    const int lane = tid & 7;
    const int b    = (blockIdx.x & 127) * 32 + (tid >> 3);
    const bool isBeta = blockIdx.x >= 128;

    const int  sA   = lane;
    const bool hasB = lane < 3;
    const int  sB   = hasB ? lane + 8 : lane;   // clamped for safe loads
    const int  sBc  = hasB ? lane + 8 : -1;     // for comparisons

    const bool isO    = (lane == 0);
    const bool isOddA = (lane & 1) != 0;
    const bool isB9   = (lane == 1);
    const bool is7    = (lane == 7);

    const float* erow  = em   + (size_t)b * TT * K;
    const int*   trow  = tags + (size_t)b * TT;
    const int4*  trow4 = (const int4*)trow;

    float rhoA, rhoB, A0, transacc, emacc;
    float QXa[8], QXb[8], QYa[8], QYb[8];

    if (!isBeta) {
        // ---------- forward over t in [0, 255] ----------
        const int rotA_ = (lane + 7) & 7;
        const float wOa = g_expT[sA * K + 0];
        const float wOb = hasB ? g_expT[sB * K + 0] : 0.0f;
        const float cCa = isOddA ? g_expT[0 * K + sA] : 0.0f;
        const float cDa = (!isOddA && sA >= 2) ? g_expT[(sA - 1) * K + sA] : 0.0f;
        const float cFa = (!isOddA && sA >= 2) ? g_expT[sA * K + sA] : 0.0f;
        const float cC9 = g_expT[0 * K + 9];
        const float cDb = (lane == 0) ? g_expT[7 * K + 8]
                        : (lane == 2) ? g_expT[9 * K + 10] : 0.0f;
        const float cFb = (lane == 0) ? g_expT[8 * K + 8]
                        : (lane == 2) ? g_expT[10 * K + 10] : 0.0f;

        int4 TXl, TXh, TYl, TYh;
        int ptag;
        ALOADC(QXa, QXb, TXl, TXh, 0)
        {
            float aA = sh_start[sA] + QXa[0];
            float aB = sh_start[sB] + QXb[0];
            float a0 = __shfl_sync(FULLM, aA, 0, 8);
            rhoA = __expf(aA - a0);
            rhoB = hasB ? __expf(aB - a0) : 0.0f;
            A0 = a0;
            int tg = TXl.x;
            transacc = sh_start[tg];
            emacc = 0.0f;
            emacc += (tg == sA)  ? QXa[0] : 0.0f;
            emacc += (tg == sBc) ? QXb[0] : 0.0f;
            ptag = tg;
        }
        ALOADC(QYa, QYb, TYl, TYh, 8)
        ASTEP(QXa[1], QXb[1], TAG8(TXl, TXh, 1))
        ASTEP(QXa[2], QXb[2], TAG8(TXl, TXh, 2))
        ASTEP(QXa[3], QXb[3], TAG8(TXl, TXh, 3))
        ASTEP(QXa[4], QXb[4], TAG8(TXl, TXh, 4))
        ASTEP(QXa[5], QXb[5], TAG8(TXl, TXh, 5))
        ASTEP(QXa[6], QXb[6], TAG8(TXl, TXh, 6))
        ASTEP(QXa[7], QXb[7], TAG8(TXl, TXh, 7))
        RENORM
#pragma unroll 1
        for (int cc = 0; cc < 15; cc++) {
            ALOADC(QXa, QXb, TXl, TXh, 16 + 16 * cc)
            APROC(QYa, QYb, TYl, TYh)
            ALOADC(QYa, QYb, TYl, TYh, 24 + 16 * cc)
            APROC(QXa, QXb, TXl, TXh)
        }
        APROC(QYa, QYb, TYl, TYh)   // t = 248..255

        float ema = emacc;
        ema += __shfl_xor_sync(FULLM, ema, 1, 8);
        ema += __shfl_xor_sync(FULLM, ema, 2, 8);
        ema += __shfl_xor_sync(FULLM, ema, 4, 8);
        g_ra[sA][b] = rhoA;
        if (hasB) g_ra[sB][b] = rhoB;
        if (lane == 0) { g_A0a[b] = A0; g_sca[b] = transacc + ema; }
    } else {
        // ---------- backward from the end down to the t=255 boundary ----------
        const int rotB_ = (lane + 1) & 7;
        const int vsrc_ = (lane == 7) ? 0 : (lane == 1) ? 2 : 0;
        const float uOa = (lane == 0 || (lane & 1)) ? g_expT[0 * K + sA] : 0.0f;
        const float uOb = (lane == 1) ? g_expT[0 * K + 9] : 0.0f;
        const float e0a = g_expT[sA * K + 0];
        const float exa = isOddA ? g_expT[sA * K + (sA + 1)] : g_expT[sA * K + sA];
        const float e0b = hasB ? g_expT[sB * K + 0] : 0.0f;
        const float exb = (lane == 0) ? g_expT[8 * K + 8]
                        : (lane == 1) ? g_expT[9 * K + 10]
                        : (lane == 2) ? g_expT[10 * K + 10] : 0.0f;

        // row length = popcount of prefix mask
        int len = 0;
        if (g_u8mode) {
            const uint4* m4 = (const uint4*)((const unsigned char*)maskp + (size_t)b * TT);
            unsigned acc = 0u;
#pragma unroll
            for (int i = lane; i < TT / 16; i += 8) {
                uint4 x = m4[i];
                acc = __dp4a(x.x, 0x01010101u, acc);
                acc = __dp4a(x.y, 0x01010101u, acc);
                acc = __dp4a(x.z, 0x01010101u, acc);
                acc = __dp4a(x.w, 0x01010101u, acc);
            }
            len = (int)acc;
        } else {
            const uint4* m4 = (const uint4*)((const unsigned*)maskp + (size_t)b * TT);
            for (int i = lane; i < TT / 4; i += 8) {
                uint4 x = m4[i];
                len += (x.x != 0u) + (x.y != 0u) + (x.z != 0u) + (x.w != 0u);
            }
        }
        len += __shfl_xor_sync(FULLM, len, 1, 8);
        len += __shfl_xor_sync(FULLM, len, 2, 8);
        len += __shfl_xor_sync(FULLM, len, 4, 8);

        const int lastTag = trow[len - 1];
        rhoA = __expf(sh_end[sA]);
        rhoB = hasB ? __expf(sh_end[sB]) : 0.0f;
        A0 = 0.0f;
        transacc = 0.0f;
        emacc = 0.0f;
        int ntag = lastTag;   // tag at position t+1 for the first valid step

        int  TXw, TYw;
        int4 TXm, TXh, TYm, TYh;
        BLOADC(QXa, QXb, TXw, TXm, TXh, 504)
        BLOADC(QYa, QYb, TYw, TYm, TYh, 496)
#pragma unroll 1
        for (int cc = 0; cc < 15; cc++) {
            int ebx = 504 - 16 * cc;
            BPROC(QXa, QXb, TXw, TXm, TXh, ebx)
            BLOADC(QXa, QXb, TXw, TXm, TXh, ebx - 16)
            BPROC(QYa, QYb, TYw, TYm, TYh, ebx - 8)
            BLOADC(QYa, QYb, TYw, TYm, TYh, ebx - 24)
        }
        BPROC(QXa, QXb, TXw, TXm, TXh, 264)
        BPROC(QYa, QYb, TYw, TYm, TYh, 256)    // produces beta at t = 255

        float emb = emacc;
        emb += __shfl_xor_sync(FULLM, emb, 1, 8);
        emb += __shfl_xor_sync(FULLM, emb, 2, 8);
        emb += __shfl_xor_sync(FULLM, emb, 4, 8);
        g_rb[sA][b] = rhoA;
        if (hasB) g_rb[sB][b] = rhoB;
        if (lane == 0) {
            g_A0b[b] = A0;
            g_scb[b] = transacc + emb + sh_end[lastTag];
        }
    }

    // ---------- last finished block performs the combine ----------
    __syncthreads();
    if (tid == 0) {
        __threadfence();
        int v = atomicAdd(&g_done, 1);
        sh_islast = (v == 255) ? 1 : 0;
    }
    __syncthreads();
    if (sh_islast) {
        float acc = 0.0f;
#pragma unroll 4
        for (int r = tid; r < BB; r += 256) {
            float dot = 0.0f;
#pragma unroll
            for (int s = 0; s < K; s++) dot = fmaf(g_ra[s][r], g_rb[s][r], dot);
            float z = g_A0a[r] + g_A0b[r] + __logf(dot);
            acc += (g_sca[r] + g_scb[r] - z);
        }
#pragma unroll
        for (int k = 16; k; k >>= 1) acc += __shfl_xor_sync(FULLM, acc, k);
        if ((tid & 31) == 0) sh_red[tid >> 5] = acc;
        __syncthreads();
        if (tid == 0) {
            float s = 0.0f;
#pragma unroll
            for (int i = 0; i < 8; i++) s += sh_red[i];
            out[0] = s * (1.0f / (float)BB);
        }
    }
}

extern "C" void kernel_launch(void* const* d_in, const int* in_sizes, int n_in,
                              void* d_out, int out_size) {
    const float* em     = (const float*)d_in[0];
    const void*  maskp  = d_in[1];
    const int*   tags   = (const int*)d_in[2];
    const float* trans  = (const float*)d_in[3];
    const float* startv = (const float*)d_in[4];
    const float* endv   = (const float*)d_in[5];
    float* out = (float*)d_out;

    setup_kernel<<<1, 128>>>(trans, startv, endv, maskp, out);
    crf_kernel<<<256, 256>>>(em, maskp, tags, out);
}

// round 10
// speedup vs baseline: 1.6841x; 1.0541x over previous
#include <cuda_runtime.h>
#include <cstdint>

#define K  11
#define TT 512
#define BB 4096
#define IMPOSSIBLE_F (-10000.0f)
#define FULLM 0xFFFFFFFFu
#define NBLK 320     // 128 alpha + 128 beta + 64 score

// Precomputed tables (written by setup kernel each launch; deterministic).
__device__ float g_transM[K * K];   // masked transitions (log, for score)
__device__ float g_expT[K * K];     // exp(masked transitions)
__device__ float g_startM[K];
__device__ float g_endM[K];
__device__ int   g_u8mode;
__device__ int   g_done;            // block-completion ticket

// Per-row scratch: alpha/beta states at the t=255 boundary + gold-path score.
__device__ float g_ra[K][BB];
__device__ float g_rb[K][BB];
__device__ float g_A0a[BB];
__device__ float g_A0b[BB];
__device__ float g_sc[BB];

__global__ void setup_kernel(const float* __restrict__ trans,
                             const float* __restrict__ startv,
                             const float* __restrict__ endv,
                             const void*  __restrict__ maskp,
                             float* __restrict__ out) {
    int t = threadIdx.x;
    if (t < K * K) {
        int i = t / K, j = t % K;
        bool allowed = (j == 0) || (j & 1) || (i == j - 1) || (i == j);
        float v = allowed ? trans[t] : IMPOSSIBLE_F;
        g_transM[t] = v;
        g_expT[t]   = expf(v);   // exp(-10000) underflows to exactly 0
    }
    if (t < K) {
        bool sforb = (t >= 2) && !(t & 1);   // cannot start with I_i
        g_startM[t] = sforb ? IMPOSSIBLE_F : startv[t];
        g_endM[t]   = endv[t];
    }
    if (t == 0) {
        // lengths >= 256 so mask[0][1] true; byte[1]!=0 iff 1-byte bool buffer
        g_u8mode = (((const unsigned char*)maskp)[1] != 0) ? 1 : 0;
        g_done = 0;
        out[0] = 0.0f;
    }
}

// ---- pairing layout: lane 0 = state O; lane j in [1,5] = (B_j, I_j);
//      lanes 6,7 idle (all weights zero -> rho stays 0). 4 shuffles/step. ----

#define RENORM                                                           \
    {                                                                    \
        float m_ = __shfl_sync(FULLM, rhoP, 0, 8);                       \
        float i_ = __frcp_rn(m_);                                        \
        rhoP *= i_; rhoQ *= i_;                                          \
        A0 += __logf(m_);                                                \
    }

// forward: rhoO' = e0 * sum_s rho_s T[s][O]; rhoB' = eB * rhoO T[O][B];
//          rhoI' = eI * (rhoB T[B][I] + rhoI T[I][I])   (lane-local)
#define ASTEP(EMP, EMQ)                                                  \
    {                                                                    \
        float eP_ = __expf(EMP), eQ_ = __expf(EMQ);                      \
        float part_ = fmaf(rhoQ, wQ0, rhoP * wP0);                       \
        part_ += __shfl_xor_sync(FULLM, part_, 1, 8);                    \
        part_ += __shfl_xor_sync(FULLM, part_, 2, 8);                    \
        part_ += __shfl_xor_sync(FULLM, part_, 4, 8);                    \
        float rO_ = __shfl_sync(FULLM, rhoP, 0, 8);                      \
        float nP_ = isO ? part_ : rO_ * cPB;                             \
        float nQ_ = fmaf(rhoP, cBI, rhoQ * cII);                         \
        rhoP = nP_ * eP_;                                                \
        rhoQ = nQ_ * eQ_;                                                \
    }

#define ALOADC(QP_, QQ_, TB)                                             \
    {                                                                    \
        _Pragma("unroll")                                                \
        for (int k_ = 0; k_ < 8; k_++) {                                 \
            int t_ = (TB) + k_;                                          \
            QP_[k_] = pP[t_ * K];                                        \
            QQ_[k_] = pQ[t_ * K];                                        \
        }                                                                \
    }

#define APROC(QP_, QQ_)                                                  \
    {                                                                    \
        ASTEP(QP_[0], QQ_[0]) ASTEP(QP_[1], QQ_[1])                      \
        ASTEP(QP_[2], QQ_[2]) ASTEP(QP_[3], QQ_[3])                      \
        ASTEP(QP_[4], QQ_[4]) ASTEP(QP_[5], QQ_[5])                      \
        ASTEP(QP_[6], QQ_[6]) ASTEP(QP_[7], QQ_[7])                      \
        RENORM                                                           \
    }

// backward: b_s = e_s beta_s; betaO' = sum_s T[O][s] b_s (only O,B cols nonzero);
//           betaB' = T[B][O] bO + T[B][I] bI; betaI' = T[I][O] bO + T[I][I] bI
#define BSTEP(EMP, EMQ, VALID)                                           \
    {                                                                    \
        float bP_ = __expf(EMP) * rhoP;                                  \
        float bQ_ = __expf(EMQ) * rhoQ;                                  \
        float part_ = bP_ * wOt;                                         \
        part_ += __shfl_xor_sync(FULLM, part_, 1, 8);                    \
        part_ += __shfl_xor_sync(FULLM, part_, 2, 8);                    \
        part_ += __shfl_xor_sync(FULLM, part_, 4, 8);                    \
        float bO_ = __shfl_sync(FULLM, bP_, 0, 8);                       \
        float nP_ = isO ? part_ : fmaf(uP0, bO_, uPI * bQ_);             \
        float nQ_ = fmaf(uQ0, bO_, uQI * bQ_);                           \
        const bool vl_ = (VALID);                                        \
        rhoP = vl_ ? nP_ : rhoP;                                         \
        rhoQ = vl_ ? nQ_ : rhoQ;                                         \
    }

#define BPROC(QP_, QQ_, EB)                                              \
    {                                                                    \
        BSTEP(QP_[7], QQ_[7], ((EB) + 7) < len)                          \
        BSTEP(QP_[6], QQ_[6], ((EB) + 6) < len)                          \
        BSTEP(QP_[5], QQ_[5], ((EB) + 5) < len)                          \
        BSTEP(QP_[4], QQ_[4], ((EB) + 4) < len)                          \
        BSTEP(QP_[3], QQ_[3], ((EB) + 3) < len)                          \
        BSTEP(QP_[2], QQ_[2], ((EB) + 2) < len)                          \
        BSTEP(QP_[1], QQ_[1], ((EB) + 1) < len)                          \
        BSTEP(QP_[0], QQ_[0], ((EB) + 0) < len)                          \
        RENORM                                                           \
    }

// Blocks [0,128): alpha (t in [0,255]).  [128,256): beta (t down to 255).
// [256,320): gold-path score (warp per row, 8 rows per warp).
// Last block (atomic ticket) does the per-row combine + mean.
__global__ void __launch_bounds__(256)
crf_kernel(const float* __restrict__ em,
           const void*  __restrict__ maskp,
           const int*   __restrict__ tags,
           float* __restrict__ out) {
    __shared__ float sh_trans[K * K];
    __shared__ float sh_start[K];
    __shared__ float sh_end[K];
    __shared__ float sh_red[8];
    __shared__ int   sh_islast;
    {
        int i = threadIdx.x;
        if (i < K * K) sh_trans[i] = g_transM[i];
        if (i >= 128 && i < 128 + K) {
            sh_start[i - 128] = g_startM[i - 128];
            sh_end[i - 128]   = g_endM[i - 128];
        }
    }
    __syncthreads();

    const int tid = threadIdx.x;
    const int bid = blockIdx.x;

    if (bid < 256) {
        // ================= recursion halves =================
        const int lane = tid & 7;
        const int b    = (bid & 127) * 32 + (tid >> 3);
        const bool isBeta = bid >= 128;

        const bool isO  = (lane == 0);
        const bool hasS = (lane >= 1) && (lane <= 5);
        const int  sP   = hasS ? 2 * lane - 1 : 0;   // B_j (lane 0: O)
        const int  sQ   = hasS ? 2 * lane     : 0;   // I_j

        const float* erow = em + (size_t)b * TT * K;
        const float* pP = erow + sP;
        const float* pQ = erow + sQ;

        float rhoP, rhoQ, A0;
        float QXp[8], QXq[8], QYp[8], QYq[8];

        if (!isBeta) {
            // ---------- forward t in [0, 255] ----------
            const float wP0 = (isO || hasS) ? g_expT[sP * K] : 0.0f; // T[s][O]
            const float wQ0 = hasS ? g_expT[sQ * K] : 0.0f;
            const float cPB = hasS ? g_expT[sP] : 0.0f;              // T[O][B]
            const float cBI = hasS ? g_expT[sP * K + sQ] : 0.0f;     // T[B][I]
            const float cII = hasS ? g_expT[sQ * K + sQ] : 0.0f;     // T[I][I]

            ALOADC(QXp, QXq, 0)
            {
                float aP = sh_start[sP] + QXp[0];
                float a0 = __shfl_sync(FULLM, aP, 0, 8);
                rhoP = (isO || hasS) ? __expf(aP - a0) : 0.0f;
                // I-states: start = -1e4 -> exp underflows to exactly 0
                rhoQ = hasS ? __expf(sh_start[sQ] + QXq[0] - a0) : 0.0f;
                A0 = a0;
            }
            ALOADC(QYp, QYq, 8)
            ASTEP(QXp[1], QXq[1]) ASTEP(QXp[2], QXq[2])
            ASTEP(QXp[3], QXq[3]) ASTEP(QXp[4], QXq[4])
            ASTEP(QXp[5], QXq[5]) ASTEP(QXp[6], QXq[6])
            ASTEP(QXp[7], QXq[7])
            RENORM
#pragma unroll 1
            for (int cc = 0; cc < 15; cc++) {
                ALOADC(QXp, QXq, 16 + 16 * cc)
                APROC(QYp, QYq)
                ALOADC(QYp, QYq, 24 + 16 * cc)
                APROC(QXp, QXq)
            }
            APROC(QYp, QYq)   // t = 248..255

            if (isO || hasS) g_ra[sP][b] = rhoP;
            if (hasS)        g_ra[sQ][b] = rhoQ;
            if (isO) g_A0a[b] = A0;
        } else {
            // ---------- backward from the end down to t = 255 ----------
            const float wOt = (isO || hasS) ? g_expT[sP] : 0.0f;     // T[O][s]
            const float uP0 = hasS ? g_expT[sP * K] : 0.0f;          // T[B][O]
            const float uPI = hasS ? g_expT[sP * K + sQ] : 0.0f;     // T[B][I]
            const float uQ0 = hasS ? g_expT[sQ * K] : 0.0f;          // T[I][O]
            const float uQI = hasS ? g_expT[sQ * K + sQ] : 0.0f;     // T[I][I]

            // row length = popcount of prefix mask
            int len = 0;
            if (g_u8mode) {
                const uint4* m4 = (const uint4*)((const unsigned char*)maskp + (size_t)b * TT);
                unsigned acc = 0u;
#pragma unroll
                for (int i = lane; i < TT / 16; i += 8) {
                    uint4 x = m4[i];
                    acc = __dp4a(x.x, 0x01010101u, acc);
                    acc = __dp4a(x.y, 0x01010101u, acc);
                    acc = __dp4a(x.z, 0x01010101u, acc);
                    acc = __dp4a(x.w, 0x01010101u, acc);
                }
                len = (int)acc;
            } else {
                const uint4* m4 = (const uint4*)((const unsigned*)maskp + (size_t)b * TT);
                for (int i = lane; i < TT / 4; i += 8) {
                    uint4 x = m4[i];
                    len += (x.x != 0u) + (x.y != 0u) + (x.z != 0u) + (x.w != 0u);
                }
            }
            len += __shfl_xor_sync(FULLM, len, 1, 8);
            len += __shfl_xor_sync(FULLM, len, 2, 8);
            len += __shfl_xor_sync(FULLM, len, 4, 8);

            rhoP = (isO || hasS) ? __expf(sh_end[sP]) : 0.0f;
            rhoQ = hasS ? __expf(sh_end[sQ]) : 0.0f;
            A0 = 0.0f;

            BLOADC_BETA:;
            BPROC_DUMMY:;
            // double-buffered descent (em index = t+1, consumed descending)
            {
                ALOADC(QXp, QXq, 504)
                ALOADC(QYp, QYq, 496)
#pragma unroll 1
                for (int cc = 0; cc < 15; cc++) {
                    int ebx = 504 - 16 * cc;
                    BPROC(QXp, QXq, ebx)
                    ALOADC(QXp, QXq, ebx - 16)
                    BPROC(QYp, QYq, ebx - 8)
                    ALOADC(QYp, QYq, ebx - 24)
                }
                BPROC(QXp, QXq, 264)
                BPROC(QYp, QYq, 256)   // beta at t = 255
            }

            if (isO || hasS) g_rb[sP][b] = rhoP;
            if (hasS)        g_rb[sQ][b] = rhoQ;
            if (isO) g_A0b[b] = A0;
        }
    } else {
        // ================= gold-path score (gather-sum, no recursion) =====
        const int wid = tid >> 5, lane32 = tid & 31;
        const int sbid = bid - 256;
#pragma unroll 1
        for (int rr = 0; rr < 8; rr++) {
            int b = (sbid * 8 + wid) * 8 + rr;
            const int*   trow = tags + (size_t)b * TT;
            const float* erow = em   + (size_t)b * TT * K;

            int len = 0;
            if (g_u8mode) {
                const uint4* m4 = (const uint4*)((const unsigned char*)maskp + (size_t)b * TT);
                uint4 x = m4[lane32];   // TT/16 == 32 == lanes
                unsigned acc = 0u;
                acc = __dp4a(x.x, 0x01010101u, acc);
                acc = __dp4a(x.y, 0x01010101u, acc);
                acc = __dp4a(x.z, 0x01010101u, acc);
                acc = __dp4a(x.w, 0x01010101u, acc);
                len = (int)acc;
            } else {
                const uint4* m4 = (const uint4*)((const unsigned*)maskp + (size_t)b * TT);
#pragma unroll
                for (int i = 0; i < 4; i++) {
                    uint4 x = m4[lane32 + 32 * i];
                    len += (x.x != 0u) + (x.y != 0u) + (x.z != 0u) + (x.w != 0u);
                }
            }
#pragma unroll
            for (int k = 16; k; k >>= 1) len += __shfl_xor_sync(FULLM, len, k);

            float acc = 0.0f;
#pragma unroll
            for (int it = 0; it < 16; it++) {
                int t = it * 32 + lane32;
                int tgc = trow[t];
                int tgp = trow[t > 0 ? t - 1 : 0];
                float ev = erow[t * K + tgc];
                bool v = (t >= 1) && (t < len);
                acc += v ? (sh_trans[tgp * K + tgc] + ev) : 0.0f;
            }
            if (lane32 == 0) {
                int tg0 = trow[0];
                acc += sh_start[tg0] + erow[tg0];
            }
#pragma unroll
            for (int k = 16; k; k >>= 1) acc += __shfl_xor_sync(FULLM, acc, k);
            if (lane32 == 0) g_sc[b] = acc + sh_end[trow[len - 1]];
        }
    }

    // ---------- last finished block performs the combine ----------
    __syncthreads();
    if (tid == 0) {
        __threadfence();
        int v = atomicAdd(&g_done, 1);
        sh_islast = (v == NBLK - 1) ? 1 : 0;
    }
    __syncthreads();
    if (sh_islast) {
        float acc = 0.0f;
#pragma unroll 4
        for (int r = tid; r < BB; r += 256) {
            float dot = 0.0f;
#pragma unroll
            for (int s = 0; s < K; s++) dot = fmaf(g_ra[s][r], g_rb[s][r], dot);
            float z = g_A0a[r] + g_A0b[r] + __logf(dot);
            acc += (g_sc[r] - z);
        }
#pragma unroll
        for (int k = 16; k; k >>= 1) acc += __shfl_xor_sync(FULLM, acc, k);
        if ((tid & 31) == 0) sh_red[tid >> 5] = acc;
        __syncthreads();
        if (tid == 0) {
            float s = 0.0f;
#pragma unroll
            for (int i = 0; i < 8; i++) s += sh_red[i];
            out[0] = s * (1.0f / (float)BB);
        }
    }
}

extern "C" void kernel_launch(void* const* d_in, const int* in_sizes, int n_in,
                              void* d_out, int out_size) {
    const float* em     = (const float*)d_in[0];
    const void*  maskp  = d_in[1];
    const int*   tags   = (const int*)d_in[2];
    const float* trans  = (const float*)d_in[3];
    const float* startv = (const float*)d_in[4];
    const float* endv   = (const float*)d_in[5];
    float* out = (float*)d_out;

    setup_kernel<<<1, 128>>>(trans, startv, endv, maskp, out);
    crf_kernel<<<NBLK, 256>>>(em, maskp, tags, out);
}